// round 13
// baseline (speedup 1.0000x reference)
#include <cuda_runtime.h>
#include <math.h>

#define BB 8
#define HH 512
#define WW 512
#define NPIX (BB*HH*WW)

#define NBLK1 (BB*HH)         // 4096 pass1 blocks (one per row)
#define NBLK2 (128*8)         // 1024 pass2 blocks (4-row x 512-col bands)
#define DSENT 30000

// Packed row-EDT distances, u8 per mask saturated at 255:
// byte0 = gt distance, byte1 = seg distance (2 bytes per pixel).
__device__ unsigned short g_pack[NPIX];
// Per-block partial sums (no hot atomics).
__device__ double g_part[NBLK1 * 4];
__device__ double g_hd[NBLK2];
__device__ unsigned g_count;   // zero-init at load; last block resets it

// Nearest-set-bit distance in a 512-bit row stored as 16 uint32 words
// (set bit == background). Returns linear distance, DSENT if none.
__device__ __forceinline__ int nz_d(const unsigned* __restrict__ z, int j) {
    int w  = j >> 5;
    int jb = j & 31;
    int dl = DSENT;
    unsigned t = z[w] & (0xFFFFFFFFu >> (31 - jb));
    if (t) {
        dl = jb - (31 - __clz(t));
    } else {
        #pragma unroll 4
        for (int ww = w - 1; ww >= 0; --ww) {
            unsigned zz = z[ww];
            if (zz) { dl = j - (ww * 32 + 31 - __clz(zz)); break; }
        }
    }
    int dr = DSENT;
    unsigned u = z[w] & (0xFFFFFFFFu << jb);
    if (u) {
        dr = (__ffs(u) - 1) - jb;
    } else {
        #pragma unroll 4
        for (int ww = w + 1; ww < 16; ++ww) {
            unsigned zz = z[ww];
            if (zz) { dr = ww * 32 + (__ffs(zz) - 1) - j; break; }
        }
    }
    return min(dl, dr);
}

// Pack per-thread 4-bit nibbles into 32-bit row-mask words.
__device__ __forceinline__ unsigned pack_nibbles(unsigned nib) {
    unsigned v = nib | (__shfl_xor_sync(0xFFFFFFFFu, nib, 1) << 4);
    v = v | (__shfl_xor_sync(0xFFFFFFFFu, v, 2) << 8);
    v = v | (__shfl_xor_sync(0xFFFFFFFFu, v, 4) << 16);
    return v;   // valid at lanes == 0 (mod 8)
}

// Cold exact tail: column search beyond radius 2 reading packed rows from
// gmem. Essentially never executed (P ~ 1e-8 per pixel).
__device__ __noinline__ void tail_scan(const unsigned short* __restrict__ Pb,
                                       int i, int j, int& g, int& s) {
    for (int r = 3; r < HH; r++) {
        int r2 = r * r;
        if (r2 >= g && r2 >= s) break;
        if (i - r >= 0) {
            unsigned cc = Pb[(size_t)(i - r) * WW + j];
            int vg = (int)(cc & 0xFFu);
            int vs = (int)(cc >> 8);
            g = min(g, vg * vg + r2);
            s = min(s, vs * vs + r2);
        }
        if (i + r < HH) {
            unsigned cc = Pb[(size_t)(i + r) * WW + j];
            int vg = (int)(cc & 0xFFu);
            int vs = (int)(cc >> 8);
            g = min(g, vg * vg + r2);
            s = min(s, vs * vs + r2);
        }
    }
}

// Pass 1: 128 threads per (batch,row), 4 pixels each (round-10 known-good).
__global__ void __launch_bounds__(128) pass1_k(const float* __restrict__ outputs,
                                               const int* __restrict__ label) {
    int row = blockIdx.x;
    int b   = blockIdx.y;
    int t   = threadIdx.x;
    int wid = t >> 5, lid = t & 31;
    int j4  = t * 4;

    __shared__ unsigned zg[16];   // set bit == (lab == 0)
    __shared__ unsigned zs[16];   // set bit == (p1 <= 0.5)

    size_t base1 = ((size_t)(b * 2 + 1) * HH + row) * WW;
    float4 p1v = *(const float4*)(outputs + base1 + j4);
    int4   lbv = *(const int4*)(label + base1 + j4);

    float p1a[4] = {p1v.x, p1v.y, p1v.z, p1v.w};
    int   lba[4] = {lbv.x, lbv.y, lbv.z, lbv.w};

    unsigned nibg = 0, nibs = 0;
    #pragma unroll
    for (int k = 0; k < 4; k++) {
        nibg |= (lba[k] > 0 ? 0u : 1u) << k;       // set bit == background
        nibs |= (p1a[k] > 0.5f ? 0u : 1u) << k;
    }
    unsigned wg = pack_nibbles(nibg);
    unsigned ws = pack_nibbles(nibs);
    if ((lid & 7) == 0) {
        int wslot = wid * 4 + (lid >> 3);
        zg[wslot] = wg;
        zs[wslot] = ws;
    }
    __syncthreads();

    unsigned pk[4];
    #pragma unroll
    for (int k = 0; k < 4; k++) {
        int dg = min(nz_d(zg, j4 + k), 255);
        int ds = min(nz_d(zs, j4 + k), 255);
        pk[k] = (unsigned)dg | ((unsigned)ds << 8);
    }
    uint2 st;
    st.x = pk[0] | (pk[1] << 16);
    st.y = pk[2] | (pk[3] << 16);
    *(uint2*)(g_pack + ((size_t)b * HH + row) * WW + j4) = st;

    // Pointwise CE/Dice terms (fast-math; p0 = 1 - p1)
    float v0 = 0.f, v1 = 0.f, v2 = 0.f, v3 = 0.f;
    #pragma unroll
    for (int k = 0; k < 4; k++) {
        float p1 = p1a[k];
        float p0 = 1.0f - p1;
        float labf = (lba[k] > 0) ? 1.0f : 0.0f;
        float mx   = fmaxf(p0, p1);
        float lse  = mx + __logf(__expf(p0 - mx) + __expf(p1 - mx));
        float picked = (lba[k] > 0) ? p1 : p0;
        v0 += p1 * labf;
        v1 += p1 * p1;
        v2 += labf;
        v3 += lse - picked;
    }

    #pragma unroll
    for (int off = 16; off > 0; off >>= 1) {
        v0 += __shfl_down_sync(0xFFFFFFFFu, v0, off);
        v1 += __shfl_down_sync(0xFFFFFFFFu, v1, off);
        v2 += __shfl_down_sync(0xFFFFFFFFu, v2, off);
        v3 += __shfl_down_sync(0xFFFFFFFFu, v3, off);
    }
    __shared__ float sb[4][4];
    if (lid == 0) { sb[wid][0] = v0; sb[wid][1] = v1; sb[wid][2] = v2; sb[wid][3] = v3; }
    __syncthreads();
    if (t < 4) {
        double s = 0.0;
        #pragma unroll
        for (int w = 0; w < 4; w++) s += (double)sb[w][t];
        g_part[(b * HH + row) * 4 + t] = s;
    }
}

// Pass 2: column EDT, 8 px/thread. Pack window staged through an 8-row smem
// tile (4 owned + 2 halo each side): 2 LDG for the tile + 2 LDG for p1 per
// thread, window reads are LDS. Rare exact tail reads gmem.
__global__ void __launch_bounds__(256) pass2_k(const float* __restrict__ outputs,
                                               float* __restrict__ out) {
    int b  = blockIdx.y;
    int y0 = blockIdx.x * 4;                 // first owned row
    int tx = threadIdx.x;                    // 0..63 (column octet)
    int ty = threadIdx.y;                    // 0..3  (row within band)
    int tid = ty * 64 + tx;
    int i   = y0 + ty;
    int j8  = tx * 8;

    const unsigned short* __restrict__ Pb = g_pack + (size_t)b * HH * WW;

    // smem tile: 8 rows (y0-2 .. y0+5, clamped) x 512 cols x 2B = 8 KB
    __shared__ unsigned short tile[8][WW];

    // p1 issued early to overlap with tile load
    size_t base1 = ((size_t)(b * 2 + 1) * HH + i) * WW + j8;
    float4 p1lo = *(const float4*)(outputs + base1);
    float4 p1hi = *(const float4*)(outputs + base1 + 4);

    // Cooperative tile load: 512 uint4 total, 2 per thread, coalesced.
    {
        uint4* ts = (uint4*)&tile[0][0];
        #pragma unroll
        for (int q = 0; q < 2; q++) {
            int idx = tid + q * 256;         // 0..511
            int r   = idx >> 6;              // smem row 0..7 (64 uint4/row)
            int c16 = idx & 63;              // uint4 within row
            int gy  = min(max(y0 - 2 + r, 0), HH - 1);
            ts[idx] = *(const uint4*)(Pb + (size_t)gy * WW + c16 * 8);
        }
    }
    __syncthreads();

    int slot = ty + 2;
    uint4 c0v = *(const uint4*)&tile[slot][j8];
    uint4 u1v = *(const uint4*)&tile[slot - 1][j8];
    uint4 d1v = *(const uint4*)&tile[slot + 1][j8];
    uint4 u2v = *(const uint4*)&tile[slot - 2][j8];
    uint4 d2v = *(const uint4*)&tile[slot + 2][j8];

    const unsigned* c0w = (const unsigned*)&c0v;
    const unsigned* u1w = (const unsigned*)&u1v;
    const unsigned* d1w = (const unsigned*)&d1v;
    const unsigned* u2w = (const unsigned*)&u2v;
    const unsigned* d2w = (const unsigned*)&d2v;

    float p1a[8] = {p1lo.x, p1lo.y, p1lo.z, p1lo.w, p1hi.x, p1hi.y, p1hi.z, p1hi.w};
    float hd = 0.f;

    #pragma unroll
    for (int k = 0; k < 4; k++) {
        unsigned m1 = __vminu4(u1w[k], d1w[k]);   // per-byte min, radius 1
        unsigned m2 = __vminu4(u2w[k], d2w[k]);   // per-byte min, radius 2
        #pragma unroll
        for (int h = 0; h < 2; h++) {
            int px = 2 * k + h;
            unsigned cw = c0w[k] >> (h * 16);
            unsigned w1 = m1 >> (h * 16);
            unsigned w2 = m2 >> (h * 16);
            int dg = (int)(cw & 0xFFu), ds = (int)((cw >> 8) & 0xFFu);
            int g1 = (int)(w1 & 0xFFu), s1 = (int)((w1 >> 8) & 0xFFu);
            int g2 = (int)(w2 & 0xFFu), s2 = (int)((w2 >> 8) & 0xFFu);
            int g = min(dg * dg, min(g1 * g1 + 1, g2 * g2 + 4));
            int s = min(ds * ds, min(s1 * s1 + 1, s2 * s2 + 4));
            if (g > 9 || s > 9)
                tail_scan(Pb, i, j8 + px, g, s);
            float labf = (dg != 0) ? 1.0f : 0.0f;   // dg>0 <=> lab>0
            float dlt  = p1a[px] - labf;
            hd += (dlt * dlt) * ((float)g + (float)s);
        }
    }

    #pragma unroll
    for (int off = 16; off > 0; off >>= 1)
        hd += __shfl_down_sync(0xFFFFFFFFu, hd, off);

    __shared__ double sbh[8];
    int wid = tid >> 5, lid = tid & 31;
    if (lid == 0) sbh[wid] = (double)hd;
    __syncthreads();

    int bid = blockIdx.y * gridDim.x + blockIdx.x;
    if (tid < 8) {
        double s = sbh[tid];
        #pragma unroll
        for (int off = 4; off > 0; off >>= 1)
            s += __shfl_down_sync(0x000000FFu, s, off);
        if (tid == 0) g_hd[bid] = s;
    }

    // ── last-block finalize ──
    __shared__ bool isLast;
    if (tid == 0) {
        __threadfence();
        unsigned cnum = atomicAdd(&g_count, 1u);
        isLast = (cnum == NBLK2 - 1);
    }
    __syncthreads();
    if (!isLast) return;
    __threadfence();

    double s0 = 0.0, s1 = 0.0, s2 = 0.0, s3 = 0.0, sh = 0.0;
    for (int k = tid; k < NBLK1; k += 256) {
        s0 += g_part[k * 4 + 0];
        s1 += g_part[k * 4 + 1];
        s2 += g_part[k * 4 + 2];
        s3 += g_part[k * 4 + 3];
    }
    for (int k = tid; k < NBLK2; k += 256) sh += g_hd[k];

    #pragma unroll
    for (int off = 16; off > 0; off >>= 1) {
        s0 += __shfl_down_sync(0xFFFFFFFFu, s0, off);
        s1 += __shfl_down_sync(0xFFFFFFFFu, s1, off);
        s2 += __shfl_down_sync(0xFFFFFFFFu, s2, off);
        s3 += __shfl_down_sync(0xFFFFFFFFu, s3, off);
        sh += __shfl_down_sync(0xFFFFFFFFu, sh, off);
    }
    __shared__ double fb[8][5];
    if (lid == 0) { fb[wid][0]=s0; fb[wid][1]=s1; fb[wid][2]=s2; fb[wid][3]=s3; fb[wid][4]=sh; }
    __syncthreads();
    if (tid == 0) {
        double a0d=0, a1d=0, a2d=0, a3d=0, ahd=0;
        #pragma unroll
        for (int w = 0; w < 8; w++) {
            a0d += fb[w][0]; a1d += fb[w][1]; a2d += fb[w][2]; a3d += fb[w][3]; ahd += fb[w][4];
        }
        double N    = (double)NPIX;
        double hdm  = ahd / N;
        double dice = 1.0 - (2.0 * a0d + 1e-6) / (a1d + a2d + 1e-6);
        double ce   = a3d / N;
        // LAM = 1.0, ALPHA = 0.5 -> loss = (ce + dice) + 0.5 * hd
        out[0] = (float)((ce + dice) + 0.5 * hdm);
        g_count = 0;   // reset for next graph replay
    }
}

extern "C" void kernel_launch(void* const* d_in, const int* in_sizes, int n_in,
                              void* d_out, int out_size) {
    const float* outputs = (const float*)d_in[0];
    const int*   label   = (const int*)d_in[1];
    float*       out     = (float*)d_out;

    dim3 g1(HH, BB);
    pass1_k<<<g1, 128>>>(outputs, label);

    dim3 b2(64, 4);   // 256 threads: 64 col-octets x 4 rows
    dim3 g2(HH / 4, BB);
    pass2_k<<<g2, b2>>>(outputs, out);
}